// round 7
// baseline (speedup 1.0000x reference)
#include <cuda_runtime.h>
#include <cstdint>

// Problem constants
#define BB   4
#define SS   2048
#define DD   768
#define NH   4
#define KK   4
#define DH   192          // DD / NH
#define MM   (BB*SS)      // 8192 GEMM rows

// Scan decomposition: cluster of 8 CTAs per (head,batch) problem
#define CS   8
#define ESL  (DH/CS)      // 24 outputs per CTA per gate
#define NT   192          // threads: 4 gates x 24 e x 2 d-halves

// Scratch (device globals; no allocation allowed)
__device__ float g_xconv[BB*SS*DD];      // 25 MB
__device__ float g_pre[4*BB*SS*DD];      // 100 MB: gate pre-activations [g][b][s][d]
__device__ float g_y[BB*SS*DD];          // 25 MB: hidden states pre-LN

__device__ __forceinline__ uint32_t smem_u32(const void* p) {
    return (uint32_t)__cvta_generic_to_shared(p);
}

__device__ __forceinline__ void mbar_init(uint32_t addr, uint32_t count) {
    asm volatile("mbarrier.init.shared.b64 [%0], %1;" :: "r"(addr), "r"(count) : "memory");
}
// Remote arrive (release, cluster scope implied by shared::cluster space)
__device__ __forceinline__ void mbar_arrive_remote(uint32_t remaddr) {
    asm volatile("mbarrier.arrive.shared::cluster.b64 _, [%0];" :: "r"(remaddr) : "memory");
}
// Parity wait with cluster-scope acquire (remote DSMEM stores must be visible)
__device__ __forceinline__ void mbar_wait_cluster(uint32_t addr, int parity) {
    asm volatile(
        "{\n\t"
        ".reg .pred P;\n\t"
        "WL_%=:\n\t"
        "mbarrier.try_wait.parity.acquire.cluster.shared::cta.b64 P, [%0], %1, 0x989680;\n\t"
        "@P bra.uni WD_%=;\n\t"
        "bra.uni WL_%=;\n\t"
        "WD_%=:\n\t"
        "}"
        :: "r"(addr), "r"(parity) : "memory");
}

// ---------------------------------------------------------------------------
// Stage 1: causal depthwise conv1d + bias + swish
// ---------------------------------------------------------------------------
__global__ void conv_swish_kernel(const float* __restrict__ x,
                                  const float* __restrict__ ck,
                                  const float* __restrict__ cb) {
    int idx = blockIdx.x * blockDim.x + threadIdx.x;
    if (idx >= BB*SS*DD) return;
    int d = idx % DD;
    int s = (idx / DD) % SS;
    float acc = cb[d];
#pragma unroll
    for (int j = 0; j < KK; j++) {
        int ss = s - (KK-1) + j;
        if (ss >= 0) acc = fmaf(x[idx + (j - (KK-1))*DD], ck[j*DD + d], acc);
    }
    g_xconv[idx] = acc / (1.f + expf(-acc));   // swish
}

// ---------------------------------------------------------------------------
// Stage 2: block-diagonal gate projections (64x64 smem-tiled fp32 GEMM)
// ---------------------------------------------------------------------------
__global__ __launch_bounds__(256)
void proj_gemm_kernel(const float* __restrict__ x,
                      const float* __restrict__ Wi, const float* __restrict__ Wf,
                      const float* __restrict__ Wz, const float* __restrict__ Wo) {
    int g = blockIdx.z >> 2;
    int h = blockIdx.z & 3;
    const float* src = (g < 2) ? g_xconv : x;
    const float* W = (g == 0) ? Wi : (g == 1) ? Wf : (g == 2) ? Wz : Wo;
    W += (size_t)h * DH * DH;

    int m0 = blockIdx.x * 64;
    int n0 = blockIdx.y * 64;
    int hcol = h * DH;

    __shared__ float As[16][64];
    __shared__ float Bs[16][64];

    int tid = threadIdx.x;
    int ty = tid >> 4, tx = tid & 15;
    float acc[4][4] = {};

    const float* Ab = src + (size_t)m0 * DD + hcol;

    for (int k0 = 0; k0 < DH; k0 += 16) {
        {   // A tile: 64 rows x 16 k
            int m  = tid >> 2;
            int kq = (tid & 3) * 4;
            float4 a4 = *(const float4*)(Ab + (size_t)m * DD + k0 + kq);
            As[kq+0][m] = a4.x; As[kq+1][m] = a4.y;
            As[kq+2][m] = a4.z; As[kq+3][m] = a4.w;
        }
        {   // B tile: 16 k x 64 e
            int k  = tid >> 4;
            int eq = (tid & 15) * 4;
            *(float4*)&Bs[k][eq] = *(const float4*)(W + (size_t)(k0+k)*DH + n0 + eq);
        }
        __syncthreads();
#pragma unroll
        for (int k = 0; k < 16; k++) {
            float a[4], bv[4];
#pragma unroll
            for (int i = 0; i < 4; i++) a[i]  = As[k][ty*4+i];
#pragma unroll
            for (int j = 0; j < 4; j++) bv[j] = Bs[k][tx*4+j];
#pragma unroll
            for (int i = 0; i < 4; i++)
#pragma unroll
                for (int j = 0; j < 4; j++)
                    acc[i][j] = fmaf(a[i], bv[j], acc[i][j]);
        }
        __syncthreads();
    }

    float* C = g_pre + (size_t)g*MM*DD + (size_t)m0*DD + hcol + n0;
#pragma unroll
    for (int i = 0; i < 4; i++) {
        float4 v = { acc[i][0], acc[i][1], acc[i][2], acc[i][3] };
        *(float4*)(C + (size_t)(ty*4+i)*DD + tx*4) = v;
    }
}

// ---------------------------------------------------------------------------
// Stage 3: sequential sLSTM scan.
// 16 independent (head,batch) problems; cluster of 8 CTAs each (128 CTAs).
// Thread mapping: tid = g*48 + e*2 + dh  (g gate, e local output, dh d-half).
// Each thread holds 96 R coefficients in registers (interleaved d-halves at
// float4 granularity so dual-broadcast LDS hits disjoint banks). Partner
// halves combine via shfl_xor(1). h exchange: warp-0 lanes 0..23 compute the
// gates, broadcast their 24-slice to all 8 CTAs via st.shared::cluster, then
// signal via remote mbarrier arrives (ping-pong pair, count=8).
// ---------------------------------------------------------------------------
__global__ void __cluster_dims__(CS, 1, 1) __launch_bounds__(NT, 1)
scan_kernel(const float* __restrict__ Rw, const float* __restrict__ cbias) {
    __shared__ __align__(16) float hbuf[2][DH];
    __shared__ float pre_s[4*ESL];
    __shared__ __align__(8) unsigned long long mbar[2];

    int tid = threadIdx.x;
    uint32_t rank;
    asm("mov.u32 %0, %%cluster_ctarank;" : "=r"(rank));
    int prob = blockIdx.x / CS;        // 0..15
    int b = prob >> 2;
    int h = prob & 3;
    int g   = tid / (2*ESL);           // gate 0..3
    int r48 = tid % (2*ESL);
    int e   = r48 >> 1;                // 0..23
    int dh  = r48 & 1;                 // d-half
    int eg  = (int)rank * ESL + e;     // e within head, 0..191

    // R registers: group q covers d4-index (2q+dh), i.e. d = (2q+dh)*4 + j
    float Rreg[96];
    const float* Rcol = Rw + ((size_t)(g*NH + h) * DH) * DH + eg;
#pragma unroll
    for (int q = 0; q < 24; q++) {
        int dbase = (2*q + dh) * 4;
#pragma unroll
        for (int j = 0; j < 4; j++)
            Rreg[4*q + j] = Rcol[(size_t)(dbase + j) * DH];
    }
    float bias = cbias[g*DD + h*DH + eg];
    const float* gp = g_pre + ((size_t)(g*BB + b) * SS) * DD + h*DH + eg;

    // DSMEM addresses
    uint32_t hb0 = smem_u32(&hbuf[0][0]);
    uint32_t mb0 = smem_u32(&mbar[0]);
    uint32_t peer_hb[CS];
#pragma unroll
    for (int p = 0; p < CS; p++)
        asm("mapa.shared::cluster.u32 %0, %1, %2;"
            : "=r"(peer_hb[p]) : "r"(hb0), "r"(p));
    uint32_t my_peer_mb = 0;
    if (tid < CS)
        asm("mapa.shared::cluster.u32 %0, %1, %2;"
            : "=r"(my_peer_mb) : "r"(mb0), "r"(tid));

    for (int i = tid; i < 2*DH; i += NT) ((float*)hbuf)[i] = 0.f;
    if (tid == 0) { mbar_init(mb0, CS); mbar_init(mb0 + 8, CS); }
    asm volatile("barrier.cluster.arrive.aligned;" ::: "memory");
    asm volatile("barrier.cluster.wait.aligned;"   ::: "memory");

    // Cell state for gate-compute threads (tid < 24 owns e = tid of this CTA)
    float c = 0.f, n = 0.f, m = 0.f;
    int eg_w = (int)rank * ESL + tid;          // only meaningful for tid < 24
    float* yout = g_y + ((size_t)b * SS) * DD + h*DH;

    float gin = gp[0];
    int ph0 = 0, ph1 = 0;

    for (int s = 0; s < SS; s++) {
        int cur = s & 1;
        if (s) {
            if (cur) { mbar_wait_cluster(mb0 + 8, ph1); ph1 ^= 1; }
            else     { mbar_wait_cluster(mb0,     ph0); ph0 ^= 1; }
        }
        // --- matvec: this thread's half-dot over 96 d values ---
        float a0 = 0.f, a1 = 0.f, a2 = 0.f, a3 = 0.f;
        const float4* h4p = (const float4*)hbuf[cur];
#pragma unroll
        for (int q = 0; q < 24; q++) {
            float4 h4 = h4p[2*q + dh];
            a0 = fmaf(Rreg[4*q+0], h4.x, a0);
            a1 = fmaf(Rreg[4*q+1], h4.y, a1);
            a2 = fmaf(Rreg[4*q+2], h4.z, a2);
            a3 = fmaf(Rreg[4*q+3], h4.w, a3);
        }
        float a = (a0 + a1) + (a2 + a3);
        a += __shfl_xor_sync(0xffffffffu, a, 1);   // combine d-halves
        float pre = a + gin + bias;
        if (s + 1 < SS) gin = gp[(size_t)(s+1) * DD];   // prefetch next step
        if (dh == 0) pre_s[g*ESL + e] = pre;
        __syncthreads();

        if (tid < ESL) {   // warp-0 lanes 0..23: gate nonlinearity + broadcast
            float it = pre_s[tid];
            float ft = pre_s[ESL   + tid];
            float zt = pre_s[2*ESL + tid];
            float ot = pre_s[3*ESL + tid];
            float mn = fmaxf(ft + m, it);
            float ia = __expf(it - mn);
            float fa = __expf(ft + m - mn);
            float t2 = __expf(-2.f * fabsf(zt));             // fast tanh, overflow-safe
            float tz = copysignf((1.f - t2) / (1.f + t2), zt);
            c = fa*c + ia*tz;
            n = fa*n + ia;
            m = mn;
            float sig = 1.f / (1.f + __expf(-ot));
            float hv = sig * c / n;
            if (s + 1 < SS) {
                // broadcast my h element to all 8 CTAs' next buffer
                uint32_t off = (uint32_t)((((cur ^ 1) * DH) + eg_w) * 4);
#pragma unroll
                for (int p = 0; p < CS; p++)
                    asm volatile("st.shared::cluster.f32 [%0], %1;"
                                 :: "r"(peer_hb[p] + off), "f"(hv) : "memory");
                __syncwarp(0x00ffffffu);
                if (tid < CS)
                    mbar_arrive_remote(my_peer_mb + (uint32_t)((cur ^ 1) * 8));
            }
            yout[(size_t)s * DD + eg_w] = hv;
        }
        // no trailing CTA barrier: next-step mbar wait includes the local
        // arrive (issued after gate compute), which protects pre_s reuse.
    }
    // no remote ops after the final wait; safe-exit barrier anyway (one-time)
    asm volatile("barrier.cluster.arrive.aligned;" ::: "memory");
    asm volatile("barrier.cluster.wait.aligned;"   ::: "memory");
}

// ---------------------------------------------------------------------------
// Stage 4: per-(b,s,head) layernorm over DH=192, scaled by gn_scale.
// ---------------------------------------------------------------------------
__global__ void ln_kernel(const float* __restrict__ gns, float* __restrict__ out) {
    int gidx = (blockIdx.x * blockDim.x + threadIdx.x) >> 5;
    int lane = threadIdx.x & 31;
    if (gidx >= BB*SS*NH) return;
    int h  = gidx & (NH-1);
    int bs = gidx >> 2;
    const float* yp = g_y + (size_t)bs * DD + h*DH;
    float v[6];
    float sum = 0.f;
#pragma unroll
    for (int i = 0; i < 6; i++) { v[i] = yp[lane + 32*i]; sum += v[i]; }
#pragma unroll
    for (int o = 16; o; o >>= 1) sum += __shfl_xor_sync(0xffffffffu, sum, o);
    float mu = sum * (1.f/DH);
    float sq = 0.f;
#pragma unroll
    for (int i = 0; i < 6; i++) { float t = v[i] - mu; sq += t*t; }
#pragma unroll
    for (int o = 16; o; o >>= 1) sq += __shfl_xor_sync(0xffffffffu, sq, o);
    float rs = rsqrtf(sq * (1.f/DH) + 1e-5f);
    float* op = out + (size_t)bs * DD + h*DH;
#pragma unroll
    for (int i = 0; i < 6; i++) {
        int e = lane + 32*i;
        op[e] = (v[i] - mu) * rs * gns[h*DH + e];
    }
}

// ---------------------------------------------------------------------------
extern "C" void kernel_launch(void* const* d_in, const int* in_sizes, int n_in,
                              void* d_out, int out_size) {
    const float* x     = (const float*)d_in[0];
    const float* ck    = (const float*)d_in[1];
    const float* cb    = (const float*)d_in[2];
    const float* Wi    = (const float*)d_in[3];
    const float* Wf    = (const float*)d_in[4];
    const float* Wz    = (const float*)d_in[5];
    const float* Wo    = (const float*)d_in[6];
    const float* R     = (const float*)d_in[7];
    const float* cbias = (const float*)d_in[8];
    const float* gns   = (const float*)d_in[9];
    float* out = (float*)d_out;

    conv_swish_kernel<<<(BB*SS*DD + 255)/256, 256>>>(x, ck, cb);

    dim3 gg(MM/64, DH/64, 16);   // (128, 3, 16)
    proj_gemm_kernel<<<gg, 256>>>(x, Wi, Wf, Wz, Wo);

    scan_kernel<<<BB*NH*CS, NT>>>(R, cbias);   // 128 CTAs, clusters of 8

    ln_kernel<<<(BB*SS*NH*32 + 255)/256, 256>>>(gns, out);
}

// round 8
// speedup vs baseline: 1.0376x; 1.0376x over previous
#include <cuda_runtime.h>
#include <cstdint>

// Problem constants
#define BB   4
#define SS   2048
#define DD   768
#define NH   4
#define KK   4
#define DH   192          // DD / NH
#define MM   (BB*SS)      // 8192 GEMM rows

// Scan decomposition: cluster of 8 CTAs per (head,batch) problem
#define CS   8
#define ESL  (DH/CS)      // 24 outputs per CTA per gate
#define NT   192          // threads: 4 gates x 24 e x 2 d-halves

// Scratch (device globals; no allocation allowed)
__device__ float g_xconv[BB*SS*DD];      // 25 MB
__device__ float g_pre[4*BB*SS*DD];      // 100 MB: gate pre-activations [g][b][s][d]
__device__ float g_y[BB*SS*DD];          // 25 MB: hidden states pre-LN

__device__ __forceinline__ uint32_t smem_u32(const void* p) {
    return (uint32_t)__cvta_generic_to_shared(p);
}
__device__ __forceinline__ void mbar_init(uint32_t addr, uint32_t count) {
    asm volatile("mbarrier.init.shared.b64 [%0], %1;" :: "r"(addr), "r"(count) : "memory");
}
// Arm: single arrival + expect tx bytes for the current pending phase
__device__ __forceinline__ void mbar_arrive_expect_tx(uint32_t addr, uint32_t tx) {
    asm volatile("mbarrier.arrive.expect_tx.shared.b64 _, [%0], %1;"
                 :: "r"(addr), "r"(tx) : "memory");
}
// One-flight remote store + completion signal on the destination CTA's mbarrier
__device__ __forceinline__ void st_async_f32(uint32_t raddr, float v, uint32_t rmbar) {
    asm volatile("st.async.shared::cluster.mbarrier::complete_tx::bytes.b32 [%0], %1, [%2];"
                 :: "r"(raddr), "r"(__float_as_uint(v)), "r"(rmbar) : "memory");
}
// Parity wait, cluster-scope acquire (makes the async stores visible)
__device__ __forceinline__ void mbar_wait_cluster(uint32_t addr, int parity) {
    asm volatile(
        "{\n\t"
        ".reg .pred P;\n\t"
        "WL_%=:\n\t"
        "mbarrier.try_wait.parity.acquire.cluster.shared::cta.b64 P, [%0], %1, 0x989680;\n\t"
        "@P bra.uni WD_%=;\n\t"
        "bra.uni WL_%=;\n\t"
        "WD_%=:\n\t"
        "}"
        :: "r"(addr), "r"(parity) : "memory");
}

// ---------------------------------------------------------------------------
// Stage 1: causal depthwise conv1d + bias + swish
// ---------------------------------------------------------------------------
__global__ void conv_swish_kernel(const float* __restrict__ x,
                                  const float* __restrict__ ck,
                                  const float* __restrict__ cb) {
    int idx = blockIdx.x * blockDim.x + threadIdx.x;
    if (idx >= BB*SS*DD) return;
    int d = idx % DD;
    int s = (idx / DD) % SS;
    float acc = cb[d];
#pragma unroll
    for (int j = 0; j < KK; j++) {
        int ss = s - (KK-1) + j;
        if (ss >= 0) acc = fmaf(x[idx + (j - (KK-1))*DD], ck[j*DD + d], acc);
    }
    g_xconv[idx] = acc / (1.f + expf(-acc));   // swish
}

// ---------------------------------------------------------------------------
// Stage 2: block-diagonal gate projections (64x64 smem-tiled fp32 GEMM)
// Vectorized smem reads: 2x LDS.128 per 16 FMA in the inner loop.
// ---------------------------------------------------------------------------
__global__ __launch_bounds__(256)
void proj_gemm_kernel(const float* __restrict__ x,
                      const float* __restrict__ Wi, const float* __restrict__ Wf,
                      const float* __restrict__ Wz, const float* __restrict__ Wo) {
    int g = blockIdx.z >> 2;
    int h = blockIdx.z & 3;
    const float* src = (g < 2) ? g_xconv : x;
    const float* W = (g == 0) ? Wi : (g == 1) ? Wf : (g == 2) ? Wz : Wo;
    W += (size_t)h * DH * DH;

    int m0 = blockIdx.x * 64;
    int n0 = blockIdx.y * 64;
    int hcol = h * DH;

    __shared__ __align__(16) float As[16][64];
    __shared__ __align__(16) float Bs[16][64];

    int tid = threadIdx.x;
    int ty = tid >> 4, tx = tid & 15;
    float acc[4][4] = {};

    const float* Ab = src + (size_t)m0 * DD + hcol;

    for (int k0 = 0; k0 < DH; k0 += 16) {
        {   // A tile: 64 rows x 16 k (transposed store)
            int m  = tid >> 2;
            int kq = (tid & 3) * 4;
            float4 a4 = *(const float4*)(Ab + (size_t)m * DD + k0 + kq);
            As[kq+0][m] = a4.x; As[kq+1][m] = a4.y;
            As[kq+2][m] = a4.z; As[kq+3][m] = a4.w;
        }
        {   // B tile: 16 k x 64 e
            int k  = tid >> 4;
            int eq = (tid & 15) * 4;
            *(float4*)&Bs[k][eq] = *(const float4*)(W + (size_t)(k0+k)*DH + n0 + eq);
        }
        __syncthreads();
#pragma unroll
        for (int k = 0; k < 16; k++) {
            float4 a4 = *(const float4*)&As[k][ty*4];
            float4 b4 = *(const float4*)&Bs[k][tx*4];
            float a[4] = {a4.x, a4.y, a4.z, a4.w};
            float bv[4] = {b4.x, b4.y, b4.z, b4.w};
#pragma unroll
            for (int i = 0; i < 4; i++)
#pragma unroll
                for (int j = 0; j < 4; j++)
                    acc[i][j] = fmaf(a[i], bv[j], acc[i][j]);
        }
        __syncthreads();
    }

    float* C = g_pre + (size_t)g*MM*DD + (size_t)m0*DD + hcol + n0;
#pragma unroll
    for (int i = 0; i < 4; i++) {
        float4 v = { acc[i][0], acc[i][1], acc[i][2], acc[i][3] };
        *(float4*)(C + (size_t)(ty*4+i)*DD + tx*4) = v;
    }
}

// ---------------------------------------------------------------------------
// Stage 3: sequential sLSTM scan.
// 16 problems x cluster of 8 CTAs (128 CTAs). tid = g*48 + e*2 + dh.
// R in registers (96/thread, interleaved d-halves); partner halves combine
// via shfl_xor(1). h exchange: warp-0 lanes 0..23 compute the gates and
// broadcast each h element to all 8 CTAs via st.async (store + mbarrier
// complete_tx in ONE DSMEM flight). Consumers wait on a ping-pong mbarrier
// pair armed with expect_tx = DH*4 bytes (the full h vector) per phase.
// ---------------------------------------------------------------------------
__global__ void __cluster_dims__(CS, 1, 1) __launch_bounds__(NT, 1)
scan_kernel(const float* __restrict__ Rw, const float* __restrict__ cbias) {
    __shared__ __align__(16) float hbuf[2][DH];
    __shared__ float pre_s[4*ESL];
    __shared__ __align__(8) unsigned long long mbar[2];

    int tid = threadIdx.x;
    uint32_t rank;
    asm("mov.u32 %0, %%cluster_ctarank;" : "=r"(rank));
    int prob = blockIdx.x / CS;        // 0..15
    int b = prob >> 2;
    int h = prob & 3;
    int g   = tid / (2*ESL);           // gate 0..3
    int r48 = tid % (2*ESL);
    int e   = r48 >> 1;                // 0..23
    int dh  = r48 & 1;                 // d-half
    int eg  = (int)rank * ESL + e;     // e within head, 0..191

    // R registers: group q covers d4-index (2q+dh), i.e. d = (2q+dh)*4 + j
    float Rreg[96];
    const float* Rcol = Rw + ((size_t)(g*NH + h) * DH) * DH + eg;
#pragma unroll
    for (int q = 0; q < 24; q++) {
        int dbase = (2*q + dh) * 4;
#pragma unroll
        for (int j = 0; j < 4; j++)
            Rreg[4*q + j] = Rcol[(size_t)(dbase + j) * DH];
    }
    float bias = cbias[g*DD + h*DH + eg];
    const float* gp = g_pre + ((size_t)(g*BB + b) * SS) * DD + h*DH + eg;

    // DSMEM addresses (peer hbuf base + peer mbar base, all 8 ranks)
    uint32_t hb0 = smem_u32(&hbuf[0][0]);
    uint32_t mb0 = smem_u32(&mbar[0]);
    uint32_t peer_hb[CS], peer_mb[CS];
#pragma unroll
    for (int p = 0; p < CS; p++) {
        asm("mapa.shared::cluster.u32 %0, %1, %2;" : "=r"(peer_hb[p]) : "r"(hb0), "r"(p));
        asm("mapa.shared::cluster.u32 %0, %1, %2;" : "=r"(peer_mb[p]) : "r"(mb0), "r"(p));
    }

    for (int i = tid; i < 2*DH; i += NT) ((float*)hbuf)[i] = 0.f;
    if (tid == 0) {
        mbar_init(mb0,     1);
        mbar_init(mb0 + 8, 1);
        // arm phase 0 of both barriers: 1 arrival + DH*4 tx bytes each
        mbar_arrive_expect_tx(mb0,     DH*4);
        mbar_arrive_expect_tx(mb0 + 8, DH*4);
    }
    asm volatile("barrier.cluster.arrive.aligned;" ::: "memory");
    asm volatile("barrier.cluster.wait.aligned;"   ::: "memory");

    // Cell state for gate-compute threads (tid < 24 owns e = tid of this CTA)
    float c = 0.f, n = 0.f, m = 0.f;
    int eg_w = (int)rank * ESL + tid;          // only meaningful for tid < 24
    float* yout = g_y + ((size_t)b * SS) * DD + h*DH;

    float gin = gp[0];
    int ph0 = 0, ph1 = 0;

    for (int s = 0; s < SS; s++) {
        int cur = s & 1;
        if (s) {
            if (cur) { mbar_wait_cluster(mb0 + 8, ph1); ph1 ^= 1;
                       if (tid == 0) mbar_arrive_expect_tx(mb0 + 8, DH*4); }
            else     { mbar_wait_cluster(mb0,     ph0); ph0 ^= 1;
                       if (tid == 0) mbar_arrive_expect_tx(mb0,     DH*4); }
        }
        // --- matvec: this thread's half-dot over 96 d values ---
        float a0 = 0.f, a1 = 0.f, a2 = 0.f, a3 = 0.f;
        const float4* h4p = (const float4*)hbuf[cur];
#pragma unroll
        for (int q = 0; q < 24; q++) {
            float4 h4 = h4p[2*q + dh];
            a0 = fmaf(Rreg[4*q+0], h4.x, a0);
            a1 = fmaf(Rreg[4*q+1], h4.y, a1);
            a2 = fmaf(Rreg[4*q+2], h4.z, a2);
            a3 = fmaf(Rreg[4*q+3], h4.w, a3);
        }
        float a = (a0 + a1) + (a2 + a3);
        a += __shfl_xor_sync(0xffffffffu, a, 1);   // combine d-halves
        float pre = a + gin + bias;
        if (s + 1 < SS) gin = gp[(size_t)(s+1) * DD];   // prefetch next step
        if (dh == 0) pre_s[g*ESL + e] = pre;
        __syncthreads();

        if (tid < ESL) {   // warp-0 lanes 0..23: gate nonlinearity + broadcast
            float it = pre_s[tid];
            float ft = pre_s[ESL   + tid];
            float zt = pre_s[2*ESL + tid];
            float ot = pre_s[3*ESL + tid];
            float mn = fmaxf(ft + m, it);
            float ia = __expf(it - mn);
            float fa = __expf(ft + m - mn);
            float t2 = __expf(-2.f * fabsf(zt));             // fast tanh, overflow-safe
            float tz = copysignf((1.f - t2) / (1.f + t2), zt);
            c = fa*c + ia*tz;
            n = fa*n + ia;
            m = mn;
            float sig = 1.f / (1.f + __expf(-ot));
            float hv = sig * c / n;
            if (s + 1 < SS) {
                // one-flight store+signal of my h element to all 8 CTAs
                uint32_t off = (uint32_t)((((cur ^ 1) * DH) + eg_w) * 4);
                uint32_t moff = (uint32_t)((cur ^ 1) * 8);
#pragma unroll
                for (int p = 0; p < CS; p++)
                    st_async_f32(peer_hb[p] + off, hv, peer_mb[p] + moff);
            }
            yout[(size_t)s * DD + eg_w] = hv;
        }
        // pre_s reuse is protected by the next-step mbar wait (phase cannot
        // flip before this CTA's warp-0 issued its st.async, which is after
        // its pre_s reads).
    }
    // all in-flight st.async consumed by the final wait; lifetime barrier:
    asm volatile("barrier.cluster.arrive.aligned;" ::: "memory");
    asm volatile("barrier.cluster.wait.aligned;"   ::: "memory");
}

// ---------------------------------------------------------------------------
// Stage 4: per-(b,s,head) layernorm over DH=192, scaled by gn_scale.
// ---------------------------------------------------------------------------
__global__ void ln_kernel(const float* __restrict__ gns, float* __restrict__ out) {
    int gidx = (blockIdx.x * blockDim.x + threadIdx.x) >> 5;
    int lane = threadIdx.x & 31;
    if (gidx >= BB*SS*NH) return;
    int h  = gidx & (NH-1);
    int bs = gidx >> 2;
    const float* yp = g_y + (size_t)bs * DD + h*DH;
    float v[6];
    float sum = 0.f;
#pragma unroll
    for (int i = 0; i < 6; i++) { v[i] = yp[lane + 32*i]; sum += v[i]; }
#pragma unroll
    for (int o = 16; o; o >>= 1) sum += __shfl_xor_sync(0xffffffffu, sum, o);
    float mu = sum * (1.f/DH);
    float sq = 0.f;
#pragma unroll
    for (int i = 0; i < 6; i++) { float t = v[i] - mu; sq += t*t; }
#pragma unroll
    for (int o = 16; o; o >>= 1) sq += __shfl_xor_sync(0xffffffffu, sq, o);
    float rs = rsqrtf(sq * (1.f/DH) + 1e-5f);
    float* op = out + (size_t)bs * DD + h*DH;
#pragma unroll
    for (int i = 0; i < 6; i++) {
        int e = lane + 32*i;
        op[e] = (v[i] - mu) * rs * gns[h*DH + e];
    }
}

// ---------------------------------------------------------------------------
extern "C" void kernel_launch(void* const* d_in, const int* in_sizes, int n_in,
                              void* d_out, int out_size) {
    const float* x     = (const float*)d_in[0];
    const float* ck    = (const float*)d_in[1];
    const float* cb    = (const float*)d_in[2];
    const float* Wi    = (const float*)d_in[3];
    const float* Wf    = (const float*)d_in[4];
    const float* Wz    = (const float*)d_in[5];
    const float* Wo    = (const float*)d_in[6];
    const float* R     = (const float*)d_in[7];
    const float* cbias = (const float*)d_in[8];
    const float* gns   = (const float*)d_in[9];
    float* out = (float*)d_out;

    conv_swish_kernel<<<(BB*SS*DD + 255)/256, 256>>>(x, ck, cb);

    dim3 gg(MM/64, DH/64, 16);   // (128, 3, 16)
    proj_gemm_kernel<<<gg, 256>>>(x, Wi, Wf, Wz, Wo);

    scan_kernel<<<BB*NH*CS, NT>>>(R, cbias);   // 128 CTAs, clusters of 8

    ln_kernel<<<(BB*SS*NH*32 + 255)/256, 256>>>(gns, out);
}